// round 1
// baseline (speedup 1.0000x reference)
#include <cuda_runtime.h>
#include <cuda_bf16.h>
#include <cstdint>

#define N 4096
#define D 512
#define ITERS 50
#define INV_REG 20.0f
#define EPS 1e-9f
#define AB (1.0f/4096.0f)

// -------- scratch (device globals: allocation-free contract) --------
__device__ float         g_cost[(size_t)N * N];   // 64 MB fp32 cost
__device__ __nv_bfloat16 g_K[(size_t)N * N];      // 32 MB bf16 kernel matrix
__device__ float         g_u[N];
__device__ float         g_v[N];
__device__ float         g_vpart[32 * N];         // K^T u partials (deterministic)
__device__ float         g_Xs[N];
__device__ float         g_Ys[N];
__device__ float         g_losspart[N];

// -------- helpers --------
__device__ __forceinline__ float blockReduceSum(float val) {
    __shared__ float sh[32];
    int lane = threadIdx.x & 31;
    int wid  = threadIdx.x >> 5;
#pragma unroll
    for (int o = 16; o; o >>= 1) val += __shfl_down_sync(0xffffffffu, val, o);
    if (lane == 0) sh[wid] = val;
    __syncthreads();
    int nw = (blockDim.x + 31) >> 5;
    val = (threadIdx.x < nw) ? sh[threadIdx.x] : 0.0f;
    if (wid == 0) {
#pragma unroll
        for (int o = 16; o; o >>= 1) val += __shfl_down_sync(0xffffffffu, val, o);
    }
    return val;  // valid in thread 0
}

// -------- kernel 1: row norms of X and Y, plus v <- 1 init --------
__global__ void norms_init_kernel(const float* __restrict__ X,
                                  const float* __restrict__ Y) {
    int row = blockIdx.x;  // 0..8191
    const float* src = (row < N) ? (X + (size_t)row * D)
                                 : (Y + (size_t)(row - N) * D);
    float4 t = ((const float4*)src)[threadIdx.x];  // 128 threads * 4 = 512
    float s = t.x * t.x + t.y * t.y + t.z * t.z + t.w * t.w;
    s = blockReduceSum(s);
    if (threadIdx.x == 0) {
        if (row < N) g_Xs[row] = s;
        else         g_Ys[row - N] = s;
    }
    if (row < 32) g_v[row * 128 + threadIdx.x] = 1.0f;
}

// -------- kernel 2: cost + K GEMM (128x128 tile, f32x2 packed FMA) --------
__global__ void __launch_bounds__(256)
cost_gemm_kernel(const float* __restrict__ X, const float* __restrict__ Y) {
    __shared__ float As[16][128];
    __shared__ float Bs[16][128];
    int tid = threadIdx.x;
    int tx = tid & 15, ty = tid >> 4;
    int bm = blockIdx.y * 128, bn = blockIdx.x * 128;

    unsigned long long acc[8][4];
#pragma unroll
    for (int i = 0; i < 8; i++)
#pragma unroll
        for (int j = 0; j < 4; j++) acc[i][j] = 0ULL;

    for (int kk = 0; kk < D; kk += 16) {
#pragma unroll
        for (int p = 0; p < 2; p++) {
            int idx = tid + p * 256;      // 0..511
            int row = idx & 127;
            int kq  = idx >> 7;           // 0..3
            float4 av = *(const float4*)(X + (size_t)(bm + row) * D + kk + kq * 4);
            As[kq * 4 + 0][row] = av.x;
            As[kq * 4 + 1][row] = av.y;
            As[kq * 4 + 2][row] = av.z;
            As[kq * 4 + 3][row] = av.w;
            float4 bv = *(const float4*)(Y + (size_t)(bn + row) * D + kk + kq * 4);
            Bs[kq * 4 + 0][row] = bv.x;
            Bs[kq * 4 + 1][row] = bv.y;
            Bs[kq * 4 + 2][row] = bv.z;
            Bs[kq * 4 + 3][row] = bv.w;
        }
        __syncthreads();
#pragma unroll
        for (int k = 0; k < 16; k++) {
            float4 a0 = *(const float4*)&As[k][ty * 4];
            float4 a1 = *(const float4*)&As[k][64 + ty * 4];
            float4 b0 = *(const float4*)&Bs[k][tx * 4];
            float4 b1 = *(const float4*)&Bs[k][64 + tx * 4];
            unsigned long long bb[4];
            bb[0] = ((const unsigned long long*)&b0)[0];
            bb[1] = ((const unsigned long long*)&b0)[1];
            bb[2] = ((const unsigned long long*)&b1)[0];
            bb[3] = ((const unsigned long long*)&b1)[1];
            float am[8] = {a0.x, a0.y, a0.z, a0.w, a1.x, a1.y, a1.z, a1.w};
#pragma unroll
            for (int m = 0; m < 8; m++) {
                unsigned long long a2;
                asm("mov.b64 %0, {%1, %1};" : "=l"(a2) : "f"(am[m]));
#pragma unroll
                for (int n2 = 0; n2 < 4; n2++) {
                    asm("fma.rn.f32x2 %0, %1, %2, %0;"
                        : "+l"(acc[m][n2]) : "l"(a2), "l"(bb[n2]));
                }
            }
        }
        __syncthreads();
    }

    // epilogue: cost = Xs + Ys - 2*dot (clamped at 0); K = exp(-cost/REG)
#pragma unroll
    for (int m = 0; m < 8; m++) {
        int row = bm + ((m < 4) ? (ty * 4 + m) : (64 + ty * 4 + (m - 4)));
        float xs = g_Xs[row];
#pragma unroll
        for (int half = 0; half < 2; half++) {
            int col = bn + ((half == 0) ? (tx * 4) : (64 + tx * 4));
            float c[4];
#pragma unroll
            for (int q = 0; q < 2; q++) {
                float2 pr = *(float2*)&acc[m][half * 2 + q];
                c[q * 2 + 0] = pr.x;
                c[q * 2 + 1] = pr.y;
            }
            float4 costv;
            float  kf[4];
#pragma unroll
            for (int q = 0; q < 4; q++) {
                float cost = xs + g_Ys[col + q] - 2.0f * c[q];
                cost = fmaxf(cost, 0.0f);
                ((float*)&costv)[q] = cost;
                kf[q] = expf(-cost * INV_REG);
            }
            *(float4*)(g_cost + (size_t)row * N + col) = costv;
            __nv_bfloat162 p0 = __floats2bfloat162_rn(kf[0], kf[1]);
            __nv_bfloat162 p1 = __floats2bfloat162_rn(kf[2], kf[3]);
            *(__nv_bfloat162*)(g_K + (size_t)row * N + col)     = p0;
            *(__nv_bfloat162*)(g_K + (size_t)row * N + col + 2) = p1;
        }
    }
}

// -------- kernel 3: u = a / (K @ v + eps), one block per row --------
__global__ void __launch_bounds__(256) u_step_kernel() {
    int i = blockIdx.x, tid = threadIdx.x;
    const uint4*  krow = (const uint4*)(g_K + (size_t)i * N);  // 512 uint4
    const float2* vv   = (const float2*)g_v;
    float s = 0.0f;
#pragma unroll
    for (int half = 0; half < 2; half++) {
        int q = half * 256 + tid;
        uint4 kb = krow[q];
        float2 f0 = __bfloat1622float2(*(__nv_bfloat162*)&kb.x);
        float2 f1 = __bfloat1622float2(*(__nv_bfloat162*)&kb.y);
        float2 f2 = __bfloat1622float2(*(__nv_bfloat162*)&kb.z);
        float2 f3 = __bfloat1622float2(*(__nv_bfloat162*)&kb.w);
        int j2 = q * 4;
        float2 v0 = vv[j2], v1 = vv[j2 + 1], v2 = vv[j2 + 2], v3 = vv[j2 + 3];
        s += f0.x * v0.x + f0.y * v0.y;
        s += f1.x * v1.x + f1.y * v1.y;
        s += f2.x * v2.x + f2.y * v2.y;
        s += f3.x * v3.x + f3.y * v3.y;
    }
    s = blockReduceSum(s);
    if (tid == 0) g_u[i] = AB / (s + EPS);
}

// -------- kernel 4: partial column sums of K^T @ u --------
__global__ void __launch_bounds__(256) v_part_kernel() {
    __shared__ float su[128];
    int tid = threadIdx.x;
    int j  = blockIdx.x * 256 + tid;
    int i0 = blockIdx.y * 128;
    if (tid < 128) su[tid] = g_u[i0 + tid];
    __syncthreads();
    const __nv_bfloat16* p = g_K + (size_t)i0 * N + j;
    float s = 0.0f;
#pragma unroll 8
    for (int ii = 0; ii < 128; ii++)
        s += __bfloat162float(p[(size_t)ii * N]) * su[ii];
    g_vpart[blockIdx.y * N + j] = s;
}

// -------- kernel 5: v = b / (sum partials + eps) --------
__global__ void v_fin_kernel() {
    int j = blockIdx.x * 256 + threadIdx.x;
    float s = 0.0f;
#pragma unroll
    for (int c = 0; c < 32; c++) s += g_vpart[c * N + j];
    g_v[j] = AB / (s + EPS);
}

// -------- kernel 6: per-row loss partials: sum_j u_i K_ij v_j cost_ij ----
__global__ void __launch_bounds__(256) loss_part_kernel() {
    int i = blockIdx.x, tid = threadIdx.x;
    float ui = g_u[i];
    const uint4*  krow = (const uint4*)(g_K + (size_t)i * N);
    const float4* crow = (const float4*)(g_cost + (size_t)i * N);
    const float2* vv   = (const float2*)g_v;
    float s = 0.0f;
#pragma unroll
    for (int half = 0; half < 2; half++) {
        int q = half * 256 + tid;
        uint4 kb = krow[q];
        float4 c0 = crow[2 * q], c1 = crow[2 * q + 1];
        float2 f0 = __bfloat1622float2(*(__nv_bfloat162*)&kb.x);
        float2 f1 = __bfloat1622float2(*(__nv_bfloat162*)&kb.y);
        float2 f2 = __bfloat1622float2(*(__nv_bfloat162*)&kb.z);
        float2 f3 = __bfloat1622float2(*(__nv_bfloat162*)&kb.w);
        int j2 = q * 4;
        float2 v0 = vv[j2], v1 = vv[j2 + 1], v2 = vv[j2 + 2], v3 = vv[j2 + 3];
        s += f0.x * v0.x * c0.x + f0.y * v0.y * c0.y;
        s += f1.x * v1.x * c0.z + f1.y * v1.y * c0.w;
        s += f2.x * v2.x * c1.x + f2.y * v2.y * c1.y;
        s += f3.x * v3.x * c1.z + f3.y * v3.y * c1.w;
    }
    s = blockReduceSum(s);
    if (tid == 0) g_losspart[i] = ui * s;
}

// -------- kernel 7: final deterministic reduction --------
__global__ void loss_fin_kernel(float* __restrict__ out) {
    float s = 0.0f;
    for (int i = threadIdx.x; i < N; i += 256) s += g_losspart[i];
    s = blockReduceSum(s);
    if (threadIdx.x == 0) out[0] = s;
}

// -------- launch --------
extern "C" void kernel_launch(void* const* d_in, const int* in_sizes, int n_in,
                              void* d_out, int out_size) {
    const float* X = (const float*)d_in[0];  // audio_features [4096,512]
    const float* Y = (const float*)d_in[1];  // text_features  [4096,512]
    float* out = (float*)d_out;

    norms_init_kernel<<<2 * N, 128>>>(X, Y);
    cost_gemm_kernel<<<dim3(32, 32), 256>>>(X, Y);

    for (int it = 0; it < ITERS; ++it) {
        u_step_kernel<<<N, 256>>>();
        v_part_kernel<<<dim3(16, 32), 256>>>();
        v_fin_kernel<<<16, 256>>>();
    }

    loss_part_kernel<<<N, 256>>>();
    loss_fin_kernel<<<1, 256>>>(out);
}

// round 2
// speedup vs baseline: 1.1473x; 1.1473x over previous
#include <cuda_runtime.h>
#include <cuda_bf16.h>
#include <cstdint>

#define N 4096
#define D 512
#define ITERS 50
#define REG 0.05f
#define INV_REG 20.0f
#define EPS 1e-9f
#define AB (1.0f/4096.0f)

#define BLOCKS_UV 128
#define ROWS_PER_BLOCK (N / BLOCKS_UV)   // 32
#define RG 4                              // rows per group (prefetch depth)

// -------- scratch (device globals: allocation-free contract) --------
__device__ __nv_bfloat16 g_K[(size_t)N * N];        // 32 MB bf16 kernel matrix
__device__ float         g_u[N];
__device__ float         g_v[N];
__device__ float         g_vpart[BLOCKS_UV * N];    // 2 MB partials (deterministic)
__device__ float         g_Xs[N];
__device__ float         g_Ys[N];
__device__ float         g_losspart[N];

// -------- helpers --------
__device__ __forceinline__ float blockReduceSum(float val) {
    __shared__ float sh[32];
    int lane = threadIdx.x & 31;
    int wid  = threadIdx.x >> 5;
#pragma unroll
    for (int o = 16; o; o >>= 1) val += __shfl_down_sync(0xffffffffu, val, o);
    if (lane == 0) sh[wid] = val;
    __syncthreads();
    int nw = (blockDim.x + 31) >> 5;
    val = (threadIdx.x < nw) ? sh[threadIdx.x] : 0.0f;
    if (wid == 0) {
#pragma unroll
        for (int o = 16; o; o >>= 1) val += __shfl_down_sync(0xffffffffu, val, o);
    }
    return val;  // valid in thread 0
}

// -------- kernel 1: row norms of X and Y, plus v <- 1 init --------
__global__ void norms_init_kernel(const float* __restrict__ X,
                                  const float* __restrict__ Y) {
    int row = blockIdx.x;  // 0..8191
    const float* src = (row < N) ? (X + (size_t)row * D)
                                 : (Y + (size_t)(row - N) * D);
    float4 t = ((const float4*)src)[threadIdx.x];  // 128 threads * 4 = 512
    float s = t.x * t.x + t.y * t.y + t.z * t.z + t.w * t.w;
    s = blockReduceSum(s);
    if (threadIdx.x == 0) {
        if (row < N) g_Xs[row] = s;
        else         g_Ys[row - N] = s;
    }
    if (row < 32) g_v[row * 128 + threadIdx.x] = 1.0f;
}

// -------- kernel 2: K GEMM (128x128 tile, f32x2 packed FMA) --------
// K_ij = exp(-max(Xs_i + Ys_j - 2*X_i.Y_j, 0) / REG), stored bf16.
// cost is NOT stored; recovered later as -REG*ln(K).
__global__ void __launch_bounds__(256)
cost_gemm_kernel(const float* __restrict__ X, const float* __restrict__ Y) {
    __shared__ float As[16][128];
    __shared__ float Bs[16][128];
    int tid = threadIdx.x;
    int tx = tid & 15, ty = tid >> 4;
    int bm = blockIdx.y * 128, bn = blockIdx.x * 128;

    unsigned long long acc[8][4];
#pragma unroll
    for (int i = 0; i < 8; i++)
#pragma unroll
        for (int j = 0; j < 4; j++) acc[i][j] = 0ULL;

    for (int kk = 0; kk < D; kk += 16) {
#pragma unroll
        for (int p = 0; p < 2; p++) {
            int idx = tid + p * 256;      // 0..511
            int row = idx & 127;
            int kq  = idx >> 7;           // 0..3
            float4 av = *(const float4*)(X + (size_t)(bm + row) * D + kk + kq * 4);
            As[kq * 4 + 0][row] = av.x;
            As[kq * 4 + 1][row] = av.y;
            As[kq * 4 + 2][row] = av.z;
            As[kq * 4 + 3][row] = av.w;
            float4 bv = *(const float4*)(Y + (size_t)(bn + row) * D + kk + kq * 4);
            Bs[kq * 4 + 0][row] = bv.x;
            Bs[kq * 4 + 1][row] = bv.y;
            Bs[kq * 4 + 2][row] = bv.z;
            Bs[kq * 4 + 3][row] = bv.w;
        }
        __syncthreads();
#pragma unroll
        for (int k = 0; k < 16; k++) {
            float4 a0 = *(const float4*)&As[k][ty * 4];
            float4 a1 = *(const float4*)&As[k][64 + ty * 4];
            float4 b0 = *(const float4*)&Bs[k][tx * 4];
            float4 b1 = *(const float4*)&Bs[k][64 + tx * 4];
            unsigned long long bb[4];
            bb[0] = ((const unsigned long long*)&b0)[0];
            bb[1] = ((const unsigned long long*)&b0)[1];
            bb[2] = ((const unsigned long long*)&b1)[0];
            bb[3] = ((const unsigned long long*)&b1)[1];
            float am[8] = {a0.x, a0.y, a0.z, a0.w, a1.x, a1.y, a1.z, a1.w};
#pragma unroll
            for (int m = 0; m < 8; m++) {
                unsigned long long a2;
                asm("mov.b64 %0, {%1, %1};" : "=l"(a2) : "f"(am[m]));
#pragma unroll
                for (int n2 = 0; n2 < 4; n2++) {
                    asm("fma.rn.f32x2 %0, %1, %2, %0;"
                        : "+l"(acc[m][n2]) : "l"(a2), "l"(bb[n2]));
                }
            }
        }
        __syncthreads();
    }

    // epilogue: K = exp(-max(Xs+Ys-2*dot, 0) * INV_REG) -> bf16
#pragma unroll
    for (int m = 0; m < 8; m++) {
        int row = bm + ((m < 4) ? (ty * 4 + m) : (64 + ty * 4 + (m - 4)));
        float xs = g_Xs[row];
#pragma unroll
        for (int half = 0; half < 2; half++) {
            int col = bn + ((half == 0) ? (tx * 4) : (64 + tx * 4));
            float c[4];
#pragma unroll
            for (int q = 0; q < 2; q++) {
                float2 pr = *(float2*)&acc[m][half * 2 + q];
                c[q * 2 + 0] = pr.x;
                c[q * 2 + 1] = pr.y;
            }
            float kf[4];
#pragma unroll
            for (int q = 0; q < 4; q++) {
                float cost = xs + g_Ys[col + q] - 2.0f * c[q];
                cost = fmaxf(cost, 0.0f);
                kf[q] = expf(-cost * INV_REG);
            }
            __nv_bfloat162 p0 = __floats2bfloat162_rn(kf[0], kf[1]);
            __nv_bfloat162 p1 = __floats2bfloat162_rn(kf[2], kf[3]);
            *(__nv_bfloat162*)(g_K + (size_t)row * N + col)     = p0;
            *(__nv_bfloat162*)(g_K + (size_t)row * N + col + 2) = p1;
        }
    }
}

// -------- kernel 3: fused u-step + v-partials in ONE pass over K --------
// For each row i: u_i = a/(K_i . v + eps); then vp_j += K_ij * u_i.
// Thread t owns columns j in [t*16, t*16+16): v and vpart stay in registers.
__global__ void __launch_bounds__(256) uv_step_kernel() {
    __shared__ float red[RG][8];
    __shared__ float ush[RG];
    int tid  = threadIdx.x;
    int lane = tid & 31, wid = tid >> 5;
    int base = blockIdx.x * ROWS_PER_BLOCK;

    // load thread-owned v columns
    float vloc[16];
    const float4* vg = (const float4*)g_v;
#pragma unroll
    for (int q = 0; q < 4; q++) {
        float4 t = vg[tid * 4 + q];
        vloc[q * 4 + 0] = t.x; vloc[q * 4 + 1] = t.y;
        vloc[q * 4 + 2] = t.z; vloc[q * 4 + 3] = t.w;
    }
    float vp[16];
#pragma unroll
    for (int q = 0; q < 16; q++) vp[q] = 0.0f;

    uint4 cur[RG][2], nxt[RG][2];
#pragma unroll
    for (int r = 0; r < RG; r++) {
        const uint4* kr = (const uint4*)(g_K + (size_t)(base + r) * N);
        cur[r][0] = kr[2 * tid];
        cur[r][1] = kr[2 * tid + 1];
    }

    for (int g0 = 0; g0 < ROWS_PER_BLOCK; g0 += RG) {
        // prefetch next row group (overlaps DRAM latency with reduce/compute)
        if (g0 + RG < ROWS_PER_BLOCK) {
#pragma unroll
            for (int r = 0; r < RG; r++) {
                const uint4* kr = (const uint4*)(g_K + (size_t)(base + g0 + RG + r) * N);
                nxt[r][0] = kr[2 * tid];
                nxt[r][1] = kr[2 * tid + 1];
            }
        }
        // per-thread partial dots over owned 16 columns
        float dot[RG];
#pragma unroll
        for (int r = 0; r < RG; r++) {
            float s = 0.0f;
            const __nv_bfloat162* kp = (const __nv_bfloat162*)&cur[r][0];
#pragma unroll
            for (int q = 0; q < 8; q++) {
                float2 f = __bfloat1622float2(kp[q]);
                s += f.x * vloc[2 * q] + f.y * vloc[2 * q + 1];
            }
            dot[r] = s;
        }
        // reduce RG dots across block
#pragma unroll
        for (int r = 0; r < RG; r++) {
            float s = dot[r];
#pragma unroll
            for (int o = 16; o; o >>= 1) s += __shfl_down_sync(0xffffffffu, s, o);
            if (lane == 0) red[r][wid] = s;
        }
        __syncthreads();
        if (tid < RG) {
            float s = 0.0f;
#pragma unroll
            for (int w = 0; w < 8; w++) s += red[tid][w];
            float u = AB / (s + EPS);
            ush[tid] = u;
            g_u[base + g0 + tid] = u;
        }
        __syncthreads();
        // accumulate v-partials from the SAME registers
#pragma unroll
        for (int r = 0; r < RG; r++) {
            float u = ush[r];
            const __nv_bfloat162* kp = (const __nv_bfloat162*)&cur[r][0];
#pragma unroll
            for (int q = 0; q < 8; q++) {
                float2 f = __bfloat1622float2(kp[q]);
                vp[2 * q]     += f.x * u;
                vp[2 * q + 1] += f.y * u;
            }
        }
#pragma unroll
        for (int r = 0; r < RG; r++) {
            cur[r][0] = nxt[r][0];
            cur[r][1] = nxt[r][1];
        }
    }

    // write deterministic per-block partials
    float4* pp = (float4*)(g_vpart + (size_t)blockIdx.x * N + tid * 16);
#pragma unroll
    for (int q = 0; q < 4; q++)
        pp[q] = make_float4(vp[4 * q], vp[4 * q + 1], vp[4 * q + 2], vp[4 * q + 3]);
}

// -------- kernel 4: v = b / (sum of partials + eps) --------
__global__ void v_fin_kernel() {
    int j = blockIdx.x * 256 + threadIdx.x;
    float s = 0.0f;
#pragma unroll 8
    for (int b = 0; b < BLOCKS_UV; b++) s += g_vpart[(size_t)b * N + j];
    g_v[j] = AB / (s + EPS);
}

// -------- kernel 5: per-row loss partials: sum_j u_i K_ij v_j cost_ij ----
// cost recovered from K: cost = max(-REG * ln(K), 0)
__global__ void __launch_bounds__(256) loss_part_kernel() {
    int i = blockIdx.x, tid = threadIdx.x;
    float ui = g_u[i];
    const uint4*  krow = (const uint4*)(g_K + (size_t)i * N);
    const float2* vv   = (const float2*)g_v;
    float s = 0.0f;
#pragma unroll
    for (int half = 0; half < 2; half++) {
        int q = half * 256 + tid;
        uint4 kb = krow[q];
        float2 f0 = __bfloat1622float2(*(__nv_bfloat162*)&kb.x);
        float2 f1 = __bfloat1622float2(*(__nv_bfloat162*)&kb.y);
        float2 f2 = __bfloat1622float2(*(__nv_bfloat162*)&kb.z);
        float2 f3 = __bfloat1622float2(*(__nv_bfloat162*)&kb.w);
        int j2 = q * 4;
        float2 v0 = vv[j2], v1 = vv[j2 + 1], v2 = vv[j2 + 2], v3 = vv[j2 + 3];
        float kf[8] = {f0.x, f0.y, f1.x, f1.y, f2.x, f2.y, f3.x, f3.y};
        float vf[8] = {v0.x, v0.y, v1.x, v1.y, v2.x, v2.y, v3.x, v3.y};
#pragma unroll
        for (int e = 0; e < 8; e++) {
            float cost = fmaxf(-REG * __logf(kf[e]), 0.0f);
            s += kf[e] * vf[e] * cost;
        }
    }
    s = blockReduceSum(s);
    if (tid == 0) g_losspart[i] = ui * s;
}

// -------- kernel 6: final deterministic reduction --------
__global__ void loss_fin_kernel(float* __restrict__ out) {
    float s = 0.0f;
    for (int i = threadIdx.x; i < N; i += 256) s += g_losspart[i];
    s = blockReduceSum(s);
    if (threadIdx.x == 0) out[0] = s;
}

// -------- launch --------
extern "C" void kernel_launch(void* const* d_in, const int* in_sizes, int n_in,
                              void* d_out, int out_size) {
    const float* X = (const float*)d_in[0];  // audio_features [4096,512]
    const float* Y = (const float*)d_in[1];  // text_features  [4096,512]
    float* out = (float*)d_out;

    norms_init_kernel<<<2 * N, 128>>>(X, Y);
    cost_gemm_kernel<<<dim3(32, 32), 256>>>(X, Y);

    for (int it = 0; it < ITERS; ++it) {
        uv_step_kernel<<<BLOCKS_UV, 256>>>();
        v_fin_kernel<<<N / 256, 256>>>();
    }

    loss_part_kernel<<<N, 256>>>();
    loss_fin_kernel<<<1, 256>>>(out);
}

// round 3
// speedup vs baseline: 1.2612x; 1.0993x over previous
#include <cuda_runtime.h>
#include <cuda_bf16.h>
#include <cstdint>

#define N 4096
#define D 512
#define ITERS 50
#define REG 0.05f
#define INV_REG 20.0f
#define EPS 1e-9f
#define AB (1.0f/4096.0f)

#define BLOCKS_UV 128
#define ROWS_PER_BLOCK (N / BLOCKS_UV)   // 32
#define RG 4                              // rows per group (prefetch depth)

// -------- scratch (device globals: allocation-free contract) --------
__device__ __nv_bfloat16 g_K[(size_t)N * N];        // 32 MB bf16 kernel matrix
__device__ float         g_u[N];
__device__ float         g_v[N];
__device__ float         g_vpart[BLOCKS_UV * N];    // 2 MB partials (deterministic)
__device__ float         g_Xs[N];
__device__ float         g_Ys[N];
__device__ float         g_losspart[N];
__device__ unsigned      g_bar_count;
__device__ unsigned      g_bar_gen;

// -------- helpers --------
__device__ __forceinline__ float blockReduceSum(float val) {
    __shared__ float sh[32];
    int lane = threadIdx.x & 31;
    int wid  = threadIdx.x >> 5;
#pragma unroll
    for (int o = 16; o; o >>= 1) val += __shfl_down_sync(0xffffffffu, val, o);
    if (lane == 0) sh[wid] = val;
    __syncthreads();
    int nw = (blockDim.x + 31) >> 5;
    val = (threadIdx.x < nw) ? sh[threadIdx.x] : 0.0f;
    if (wid == 0) {
#pragma unroll
        for (int o = 16; o; o >>= 1) val += __shfl_down_sync(0xffffffffu, val, o);
    }
    return val;  // valid in thread 0
}

// software grid barrier (classic count+generation, self-resetting)
__device__ __forceinline__ void grid_barrier() {
    __threadfence();          // make this block's writes visible at L2
    __syncthreads();
    if (threadIdx.x == 0) {
        unsigned gen = *((volatile unsigned*)&g_bar_gen);
        unsigned old = atomicAdd(&g_bar_count, 1u);
        if (old == BLOCKS_UV - 1) {
            g_bar_count = 0;                 // all arrived; safe to reset
            __threadfence();
            atomicAdd(&g_bar_gen, 1u);       // release
        } else {
            while (*((volatile unsigned*)&g_bar_gen) == gen) __nanosleep(64);
        }
        __threadfence();      // acquire: order subsequent reads
    }
    __syncthreads();
}

// -------- kernel 1: row norms of X and Y, v <- 1, barrier reset --------
__global__ void norms_init_kernel(const float* __restrict__ X,
                                  const float* __restrict__ Y) {
    int row = blockIdx.x;  // 0..8191
    if (row == 0 && threadIdx.x == 0) { g_bar_count = 0; }
    const float* src = (row < N) ? (X + (size_t)row * D)
                                 : (Y + (size_t)(row - N) * D);
    float4 t = ((const float4*)src)[threadIdx.x];  // 128 threads * 4 = 512
    float s = t.x * t.x + t.y * t.y + t.z * t.z + t.w * t.w;
    s = blockReduceSum(s);
    if (threadIdx.x == 0) {
        if (row < N) g_Xs[row] = s;
        else         g_Ys[row - N] = s;
    }
    if (row < 32) g_v[row * 128 + threadIdx.x] = 1.0f;
}

// -------- kernel 2: K GEMM (128x128 tile, f32x2 packed FMA) --------
// K_ij = exp(-max(Xs_i + Ys_j - 2*X_i.Y_j, 0) / REG), stored bf16.
__global__ void __launch_bounds__(256)
cost_gemm_kernel(const float* __restrict__ X, const float* __restrict__ Y) {
    __shared__ float As[16][128];
    __shared__ float Bs[16][128];
    int tid = threadIdx.x;
    int tx = tid & 15, ty = tid >> 4;
    int bm = blockIdx.y * 128, bn = blockIdx.x * 128;

    unsigned long long acc[8][4];
#pragma unroll
    for (int i = 0; i < 8; i++)
#pragma unroll
        for (int j = 0; j < 4; j++) acc[i][j] = 0ULL;

    for (int kk = 0; kk < D; kk += 16) {
#pragma unroll
        for (int p = 0; p < 2; p++) {
            int idx = tid + p * 256;      // 0..511
            int row = idx & 127;
            int kq  = idx >> 7;           // 0..3
            float4 av = *(const float4*)(X + (size_t)(bm + row) * D + kk + kq * 4);
            As[kq * 4 + 0][row] = av.x;
            As[kq * 4 + 1][row] = av.y;
            As[kq * 4 + 2][row] = av.z;
            As[kq * 4 + 3][row] = av.w;
            float4 bv = *(const float4*)(Y + (size_t)(bn + row) * D + kk + kq * 4);
            Bs[kq * 4 + 0][row] = bv.x;
            Bs[kq * 4 + 1][row] = bv.y;
            Bs[kq * 4 + 2][row] = bv.z;
            Bs[kq * 4 + 3][row] = bv.w;
        }
        __syncthreads();
#pragma unroll
        for (int k = 0; k < 16; k++) {
            float4 a0 = *(const float4*)&As[k][ty * 4];
            float4 a1 = *(const float4*)&As[k][64 + ty * 4];
            float4 b0 = *(const float4*)&Bs[k][tx * 4];
            float4 b1 = *(const float4*)&Bs[k][64 + tx * 4];
            unsigned long long bb[4];
            bb[0] = ((const unsigned long long*)&b0)[0];
            bb[1] = ((const unsigned long long*)&b0)[1];
            bb[2] = ((const unsigned long long*)&b1)[0];
            bb[3] = ((const unsigned long long*)&b1)[1];
            float am[8] = {a0.x, a0.y, a0.z, a0.w, a1.x, a1.y, a1.z, a1.w};
#pragma unroll
            for (int m = 0; m < 8; m++) {
                unsigned long long a2;
                asm("mov.b64 %0, {%1, %1};" : "=l"(a2) : "f"(am[m]));
#pragma unroll
                for (int n2 = 0; n2 < 4; n2++) {
                    asm("fma.rn.f32x2 %0, %1, %2, %0;"
                        : "+l"(acc[m][n2]) : "l"(a2), "l"(bb[n2]));
                }
            }
        }
        __syncthreads();
    }

#pragma unroll
    for (int m = 0; m < 8; m++) {
        int row = bm + ((m < 4) ? (ty * 4 + m) : (64 + ty * 4 + (m - 4)));
        float xs = g_Xs[row];
#pragma unroll
        for (int half = 0; half < 2; half++) {
            int col = bn + ((half == 0) ? (tx * 4) : (64 + tx * 4));
            float c[4];
#pragma unroll
            for (int q = 0; q < 2; q++) {
                float2 pr = *(float2*)&acc[m][half * 2 + q];
                c[q * 2 + 0] = pr.x;
                c[q * 2 + 1] = pr.y;
            }
            float kf[4];
#pragma unroll
            for (int q = 0; q < 4; q++) {
                float cost = xs + g_Ys[col + q] - 2.0f * c[q];
                cost = fmaxf(cost, 0.0f);
                kf[q] = expf(-cost * INV_REG);
            }
            __nv_bfloat162 p0 = __floats2bfloat162_rn(kf[0], kf[1]);
            __nv_bfloat162 p1 = __floats2bfloat162_rn(kf[2], kf[3]);
            *(__nv_bfloat162*)(g_K + (size_t)row * N + col)     = p0;
            *(__nv_bfloat162*)(g_K + (size_t)row * N + col + 2) = p1;
        }
    }
}

// -------- kernel 3: PERSISTENT Sinkhorn loop (50 iterations, 1 launch) ----
// Phase A: block b handles rows [b*32, b*32+32): u_i = a/(K_i.v + eps),
//          accumulate vp_j += K_ij * u_i in registers (thread owns 16 cols).
// Phase B: block b reduces partials for columns [b*32, b*32+32) -> v_j.
__global__ void __launch_bounds__(256) sinkhorn_kernel() {
    __shared__ float red[RG][8];
    __shared__ float ush[RG];
    __shared__ float vred[8][32];
    int tid  = threadIdx.x;
    int lane = tid & 31, wid = tid >> 5;
    int base = blockIdx.x * ROWS_PER_BLOCK;

    for (int it = 0; it < ITERS; ++it) {
        // ---- Phase A ----
        float vloc[16];
        const float4* vg = (const float4*)g_v;
#pragma unroll
        for (int q = 0; q < 4; q++) {
            float4 t = __ldcg(&vg[tid * 4 + q]);
            vloc[q * 4 + 0] = t.x; vloc[q * 4 + 1] = t.y;
            vloc[q * 4 + 2] = t.z; vloc[q * 4 + 3] = t.w;
        }
        float vp[16];
#pragma unroll
        for (int q = 0; q < 16; q++) vp[q] = 0.0f;

        uint4 cur[RG][2], nxt[RG][2];
#pragma unroll
        for (int r = 0; r < RG; r++) {
            const uint4* kr = (const uint4*)(g_K + (size_t)(base + r) * N);
            cur[r][0] = __ldg(&kr[2 * tid]);
            cur[r][1] = __ldg(&kr[2 * tid + 1]);
        }

        for (int g0 = 0; g0 < ROWS_PER_BLOCK; g0 += RG) {
            if (g0 + RG < ROWS_PER_BLOCK) {
#pragma unroll
                for (int r = 0; r < RG; r++) {
                    const uint4* kr = (const uint4*)(g_K + (size_t)(base + g0 + RG + r) * N);
                    nxt[r][0] = __ldg(&kr[2 * tid]);
                    nxt[r][1] = __ldg(&kr[2 * tid + 1]);
                }
            }
            float dot[RG];
#pragma unroll
            for (int r = 0; r < RG; r++) {
                float s = 0.0f;
                const __nv_bfloat162* kp = (const __nv_bfloat162*)&cur[r][0];
#pragma unroll
                for (int q = 0; q < 8; q++) {
                    float2 f = __bfloat1622float2(kp[q]);
                    s += f.x * vloc[2 * q] + f.y * vloc[2 * q + 1];
                }
                dot[r] = s;
            }
#pragma unroll
            for (int r = 0; r < RG; r++) {
                float s = dot[r];
#pragma unroll
                for (int o = 16; o; o >>= 1) s += __shfl_down_sync(0xffffffffu, s, o);
                if (lane == 0) red[r][wid] = s;
            }
            __syncthreads();
            if (tid < RG) {
                float s = 0.0f;
#pragma unroll
                for (int w = 0; w < 8; w++) s += red[tid][w];
                float u = AB / (s + EPS);
                ush[tid] = u;
                g_u[base + g0 + tid] = u;
            }
            __syncthreads();
#pragma unroll
            for (int r = 0; r < RG; r++) {
                float u = ush[r];
                const __nv_bfloat162* kp = (const __nv_bfloat162*)&cur[r][0];
#pragma unroll
                for (int q = 0; q < 8; q++) {
                    float2 f = __bfloat1622float2(kp[q]);
                    vp[2 * q]     += f.x * u;
                    vp[2 * q + 1] += f.y * u;
                }
            }
#pragma unroll
            for (int r = 0; r < RG; r++) {
                cur[r][0] = nxt[r][0];
                cur[r][1] = nxt[r][1];
            }
        }
        float4* pp = (float4*)(g_vpart + (size_t)blockIdx.x * N + tid * 16);
#pragma unroll
        for (int q = 0; q < 4; q++)
            pp[q] = make_float4(vp[4 * q], vp[4 * q + 1], vp[4 * q + 2], vp[4 * q + 3]);

        grid_barrier();

        // ---- Phase B: v for columns [blockIdx.x*32, +32) ----
        {
            int jj = tid & 31, bg = tid >> 5;      // 8 groups x 32 cols
            int j = blockIdx.x * 32 + jj;
            float s = 0.0f;
#pragma unroll
            for (int k = 0; k < BLOCKS_UV / 8; k++) {  // 16 partials per thread
                int b = bg * (BLOCKS_UV / 8) + k;
                s += __ldcg(&g_vpart[(size_t)b * N + j]);
            }
            vred[bg][jj] = s;
            __syncthreads();
            if (tid < 32) {
                float t = 0.0f;
#pragma unroll
                for (int w = 0; w < 8; w++) t += vred[w][tid];
                g_v[blockIdx.x * 32 + tid] = AB / (t + EPS);
            }
        }

        grid_barrier();
    }
}

// -------- kernel 4: per-row loss partials: sum_j u_i K_ij v_j cost_ij ----
// cost recovered from K: cost = max(-REG * ln(K), 0)
__global__ void __launch_bounds__(256) loss_part_kernel() {
    int i = blockIdx.x, tid = threadIdx.x;
    float ui = g_u[i];
    const uint4*  krow = (const uint4*)(g_K + (size_t)i * N);
    const float2* vv   = (const float2*)g_v;
    float s = 0.0f;
#pragma unroll
    for (int half = 0; half < 2; half++) {
        int q = half * 256 + tid;
        uint4 kb = krow[q];
        float2 f0 = __bfloat1622float2(*(__nv_bfloat162*)&kb.x);
        float2 f1 = __bfloat1622float2(*(__nv_bfloat162*)&kb.y);
        float2 f2 = __bfloat1622float2(*(__nv_bfloat162*)&kb.z);
        float2 f3 = __bfloat1622float2(*(__nv_bfloat162*)&kb.w);
        int j2 = q * 4;
        float2 v0 = vv[j2], v1 = vv[j2 + 1], v2 = vv[j2 + 2], v3 = vv[j2 + 3];
        float kf[8] = {f0.x, f0.y, f1.x, f1.y, f2.x, f2.y, f3.x, f3.y};
        float vf[8] = {v0.x, v0.y, v1.x, v1.y, v2.x, v2.y, v3.x, v3.y};
#pragma unroll
        for (int e = 0; e < 8; e++) {
            float cost = fmaxf(-REG * __logf(kf[e]), 0.0f);
            s += kf[e] * vf[e] * cost;
        }
    }
    s = blockReduceSum(s);
    if (tid == 0) g_losspart[i] = ui * s;
}

// -------- kernel 5: final deterministic reduction --------
__global__ void loss_fin_kernel(float* __restrict__ out) {
    float s = 0.0f;
    for (int i = threadIdx.x; i < N; i += 256) s += g_losspart[i];
    s = blockReduceSum(s);
    if (threadIdx.x == 0) out[0] = s;
}

// -------- launch --------
extern "C" void kernel_launch(void* const* d_in, const int* in_sizes, int n_in,
                              void* d_out, int out_size) {
    const float* X = (const float*)d_in[0];  // audio_features [4096,512]
    const float* Y = (const float*)d_in[1];  // text_features  [4096,512]
    float* out = (float*)d_out;

    norms_init_kernel<<<2 * N, 128>>>(X, Y);
    cost_gemm_kernel<<<dim3(32, 32), 256>>>(X, Y);
    sinkhorn_kernel<<<BLOCKS_UV, 256>>>();
    loss_part_kernel<<<N, 256>>>();
    loss_fin_kernel<<<1, 256>>>(out);
}